// round 1
// baseline (speedup 1.0000x reference)
#include <cuda_runtime.h>

// GAE: advantages/targets, B=4096 rows, T=8192 timesteps.
// delta_t = r_t + GAMMA * v_{t+1} - v_t
// A_t = delta_t + COEF * A_{t+1}   (reverse scan, COEF = GAMMA*LAMBDA)
// targets_t = v_t + A_t
// Output layout: [advantages (B*T) | targets (B*T)] float32.

constexpr int   B_CONST  = 4096;
constexpr int   T_CONST  = 8192;
constexpr float GAMMA    = 0.99f;
constexpr float COEF     = 0.99f * 0.95f;  // gamma * lambda
constexpr int   THREADS  = 256;
constexpr int   SEG      = T_CONST / THREADS;       // 32 elements per thread
constexpr int   TPAD     = T_CONST + T_CONST / 32;  // +1 pad float per 32 -> conflict-free

__device__ __forceinline__ int padi(int t) { return t + (t >> 5); }

__global__ __launch_bounds__(THREADS)
void gae_kernel(const float* __restrict__ rewards,
                const float* __restrict__ values,
                float* __restrict__ adv_out,
                float* __restrict__ tgt_out)
{
    extern __shared__ float sh[];
    float* D = sh;          // deltas, then overwritten with advantages (TPAD floats)
    float* V = sh + TPAD;   // v_t for targets (TPAD floats)
    __shared__ float sa[THREADS];
    __shared__ float sm_[THREADS];

    const int row = blockIdx.x;
    const int tid = threadIdx.x;
    const float* r = rewards + (size_t)row * T_CONST;
    const float* v = values  + (size_t)row * (T_CONST + 1);

    // Phase 1: coalesced load + delta into padded shared memory.
    // v[t+1] re-read hits L1/L2; HBM sees each value once.
    #pragma unroll 4
    for (int t = tid; t < T_CONST; t += THREADS) {
        float vt  = __ldg(v + t);
        float vt1 = __ldg(v + t + 1);
        float dt  = __ldg(r + t) + GAMMA * vt1 - vt;
        int p = padi(t);
        V[p] = vt;
        D[p] = dt;
    }
    __syncthreads();

    // Phase 2: per-thread local reverse scan of its contiguous 32-elem segment,
    // zero carry. Padded indexing -> bank (tid + k) % 32, conflict-free.
    const int base = tid * SEG;
    float a = 0.0f;
    #pragma unroll
    for (int k = SEG - 1; k >= 0; --k)
        a = D[padi(base + k)] + COEF * a;

    // m = COEF^32 via 5 squarings
    float m = COEF;
    m *= m; m *= m; m *= m; m *= m; m *= m;

    sa[tid]  = a;
    sm_[tid] = m;
    __syncthreads();

    // Phase 3: Kogge-Stone REVERSE inclusive scan of affine maps over 256 segments.
    // (a1,m1) o (a2,m2) applied as f1(f2(x)) = (a1 + m1*a2) + (m1*m2)*x
    #pragma unroll
    for (int d = 1; d < THREADS; d <<= 1) {
        float a2 = 0.0f, m2 = 1.0f;
        const bool valid = (tid + d) < THREADS;
        if (valid) { a2 = sa[tid + d]; m2 = sm_[tid + d]; }
        __syncthreads();
        if (valid) { a = a + m * a2; m = m * m2; }
        sa[tid]  = a;
        sm_[tid] = m;
        __syncthreads();
    }

    // carry into segment tid = A at first index of segment tid+1 (true terminal carry 0)
    const float carry = (tid < THREADS - 1) ? sa[tid + 1] : 0.0f;

    // Phase 4: exact sequential recurrence within segment, seeded with true carry.
    float acc = carry;
    #pragma unroll
    for (int k = SEG - 1; k >= 0; --k) {
        int p = padi(base + k);
        acc = D[p] + COEF * acc;
        D[p] = acc;   // overwrite delta with advantage
    }
    __syncthreads();

    // Phase 5: coalesced vectorized output. 4 consecutive t share the same pad
    // offset (4 | 32), so D[p..p+3] is contiguous; lanes hit distinct banks.
    float* arow = adv_out + (size_t)row * T_CONST;
    float* trow = tgt_out + (size_t)row * T_CONST;
    #pragma unroll 2
    for (int i = tid; i < T_CONST / 4; i += THREADS) {
        int t = i * 4;
        int p = padi(t);
        float4 a4 = make_float4(D[p], D[p + 1], D[p + 2], D[p + 3]);
        float4 g4 = make_float4(V[p]     + a4.x,
                                V[p + 1] + a4.y,
                                V[p + 2] + a4.z,
                                V[p + 3] + a4.w);
        *reinterpret_cast<float4*>(arow + t) = a4;
        *reinterpret_cast<float4*>(trow + t) = g4;
    }
}

extern "C" void kernel_launch(void* const* d_in, const int* in_sizes, int n_in,
                              void* d_out, int out_size)
{
    const float* rewards = (const float*)d_in[0];   // [B, T]
    const float* values  = (const float*)d_in[1];   // [B, T+1]
    float* adv = (float*)d_out;                     // [B, T]
    float* tgt = adv + (size_t)B_CONST * T_CONST;   // [B, T]

    const int smem_bytes = 2 * TPAD * (int)sizeof(float);  // ~66 KB > 48 KB default
    cudaFuncSetAttribute(gae_kernel, cudaFuncAttributeMaxDynamicSharedMemorySize, smem_bytes);

    gae_kernel<<<B_CONST, THREADS, smem_bytes>>>(rewards, values, adv, tgt);
}

// round 2
// speedup vs baseline: 1.2782x; 1.2782x over previous
#include <cuda_runtime.h>

// GAE: advantages/targets, B=4096 rows, T=8192 timesteps.
// delta_t = r_t + GAMMA * v_{t+1} - v_t
// A_t = delta_t + COEF * A_{t+1}   (reverse scan, COEF = GAMMA*LAMBDA)
// targets_t = v_t + A_t
// Output layout: [advantages (B*T) | targets (B*T)] float32.
//
// R2: 512 threads/CTA, SEG=16, single padded smem array (deltas->advantages,
// 33KB). values re-read from global (L2-hit) for targets. 4 CTAs/SM = 64 warps.

constexpr int   B_CONST  = 4096;
constexpr int   T_CONST  = 8192;
constexpr float GAMMA    = 0.99f;
constexpr float COEF     = 0.99f * 0.95f;           // gamma * lambda
constexpr int   THREADS  = 512;
constexpr int   SEG      = T_CONST / THREADS;       // 16 elements per thread
constexpr int   TPAD     = T_CONST + T_CONST / 32;  // +1 pad float per 32

__device__ __forceinline__ int padi(int t) { return t + (t >> 5); }

__global__ __launch_bounds__(THREADS, 4)
void gae_kernel(const float* __restrict__ rewards,
                const float* __restrict__ values,
                float* __restrict__ adv_out,
                float* __restrict__ tgt_out)
{
    extern __shared__ float D[];     // TPAD floats: deltas, then advantages
    __shared__ float sa[THREADS];
    __shared__ float sm_[THREADS];

    const int row = blockIdx.x;
    const int tid = threadIdx.x;
    const float* r = rewards + (size_t)row * T_CONST;
    const float* v = values  + (size_t)row * (T_CONST + 1);

    // Phase 1: coalesced vectorized load + delta into padded smem.
    // rewards rows are 16B-aligned -> float4. values rows are 4B-aligned -> scalar.
    #pragma unroll
    for (int i = 0; i < T_CONST / (4 * THREADS); ++i) {
        int t = 4 * (tid + i * THREADS);
        float4 r4 = *reinterpret_cast<const float4*>(r + t);
        float v0 = __ldg(v + t);
        float v1 = __ldg(v + t + 1);
        float v2 = __ldg(v + t + 2);
        float v3 = __ldg(v + t + 3);
        float v4 = __ldg(v + t + 4);
        int p = padi(t);   // 4|t and t%32<=28 -> p..p+3 contiguous
        D[p]     = r4.x + GAMMA * v1 - v0;
        D[p + 1] = r4.y + GAMMA * v2 - v1;
        D[p + 2] = r4.z + GAMMA * v3 - v2;
        D[p + 3] = r4.w + GAMMA * v4 - v3;
    }
    __syncthreads();

    // Phase 2: per-thread local reverse scan of contiguous SEG=16 segment,
    // zero carry. Padded indexing -> conflict-free strided reads.
    const int base = tid * SEG;
    float a = 0.0f;
    #pragma unroll
    for (int k = SEG - 1; k >= 0; --k)
        a = D[padi(base + k)] + COEF * a;

    // m = COEF^16 via 4 squarings
    float m = COEF;
    m *= m; m *= m; m *= m; m *= m;

    sa[tid]  = a;
    sm_[tid] = m;
    __syncthreads();

    // Phase 3: Kogge-Stone REVERSE inclusive scan of affine maps (512 segs).
    #pragma unroll
    for (int d = 1; d < THREADS; d <<= 1) {
        float a2 = 0.0f, m2 = 1.0f;
        const bool valid = (tid + d) < THREADS;
        if (valid) { a2 = sa[tid + d]; m2 = sm_[tid + d]; }
        __syncthreads();
        if (valid) { a = a + m * a2; m = m * m2; }
        sa[tid]  = a;
        sm_[tid] = m;
        __syncthreads();
    }

    // carry into segment tid = advantage at first index of segment tid+1
    const float carry = (tid < THREADS - 1) ? sa[tid + 1] : 0.0f;

    // Phase 4: exact sequential recurrence within segment, seeded with carry.
    float acc = carry;
    #pragma unroll
    for (int k = SEG - 1; k >= 0; --k) {
        int p = padi(base + k);
        acc = D[p] + COEF * acc;
        D[p] = acc;   // delta -> advantage
    }
    __syncthreads();

    // Phase 5: coalesced float4 output; values re-read (L2 hit) for targets.
    float* arow = adv_out + (size_t)row * T_CONST;
    float* trow = tgt_out + (size_t)row * T_CONST;
    #pragma unroll
    for (int i = 0; i < T_CONST / (4 * THREADS); ++i) {
        int t = 4 * (tid + i * THREADS);
        int p = padi(t);
        float4 a4 = make_float4(D[p], D[p + 1], D[p + 2], D[p + 3]);
        float4 g4 = make_float4(__ldg(v + t)     + a4.x,
                                __ldg(v + t + 1) + a4.y,
                                __ldg(v + t + 2) + a4.z,
                                __ldg(v + t + 3) + a4.w);
        *reinterpret_cast<float4*>(arow + t) = a4;
        *reinterpret_cast<float4*>(trow + t) = g4;
    }
}

extern "C" void kernel_launch(void* const* d_in, const int* in_sizes, int n_in,
                              void* d_out, int out_size)
{
    const float* rewards = (const float*)d_in[0];   // [B, T]
    const float* values  = (const float*)d_in[1];   // [B, T+1]
    float* adv = (float*)d_out;                     // [B, T]
    float* tgt = adv + (size_t)B_CONST * T_CONST;   // [B, T]

    const int smem_bytes = TPAD * (int)sizeof(float);  // ~33 KB
    cudaFuncSetAttribute(gae_kernel, cudaFuncAttributeMaxDynamicSharedMemorySize, smem_bytes);

    gae_kernel<<<B_CONST, THREADS, smem_bytes>>>(rewards, values, adv, tgt);
}